// round 3
// baseline (speedup 1.0000x reference)
#include <cuda_runtime.h>
#include <cstdint>

#define N_NODES 131072
#define DIM     128
#define E_EDGES 4194304

// Scratch for y = x @ W^T  (64 MB). Static __device__ array per harness rules.
__device__ float g_y[(size_t)N_NODES * DIM];

// ---------------------------------------------------------------------------
// Kernel 1: y = x @ W^T   (y[r][c] = sum_k x[r][k] * W[c][k])
// Block: 256 threads, 32 rows per block, thread tile = 4 rows x 4 cols.
// Wt staged in SMEM k-major with stride 132 (pad kills transpose bank
// conflicts), x tile staged in SMEM (warp-broadcast reads).
// ---------------------------------------------------------------------------
#define RB 32
#define WT_STRIDE 132

__global__ void __launch_bounds__(256) gemm_xwt_kernel(
    const float* __restrict__ x, const float* __restrict__ W,
    float* __restrict__ y)
{
    extern __shared__ float smem[];
    float* Wts = smem;                    // [128][WT_STRIDE]: Wts[k*132+c] = W[c][k]
    float* xs  = smem + 128 * WT_STRIDE;  // [RB][128]

    const int tid = threadIdx.x;
    const int tx  = tid & 31;   // col group (4 cols)
    const int ty  = tid >> 5;   // row group (4 rows)
    const int row0 = blockIdx.x * RB;

    // Load W transposed into padded SMEM (gmem reads coalesced).
    #pragma unroll
    for (int i = tid; i < 128 * 128; i += 256) {
        int c = i >> 7;
        int k = i & 127;
        Wts[k * WT_STRIDE + c] = W[i];
    }
    // Load x tile (float4, coalesced).
    {
        const float4* xg = (const float4*)(x + (size_t)row0 * DIM);
        float4* xs4 = (float4*)xs;
        #pragma unroll
        for (int i = tid; i < RB * DIM / 4; i += 256) xs4[i] = xg[i];
    }
    __syncthreads();

    float acc[4][4];
    #pragma unroll
    for (int j = 0; j < 4; j++)
        #pragma unroll
        for (int c = 0; c < 4; c++) acc[j][c] = 0.f;

    #pragma unroll 4
    for (int k = 0; k < 128; k++) {
        const float4 w = *(const float4*)&Wts[k * WT_STRIDE + tx * 4];
        #pragma unroll
        for (int j = 0; j < 4; j++) {
            const float xv = xs[(ty * 4 + j) * DIM + k];  // warp-broadcast
            acc[j][0] += xv * w.x;
            acc[j][1] += xv * w.y;
            acc[j][2] += xv * w.z;
            acc[j][3] += xv * w.w;
        }
    }

    #pragma unroll
    for (int j = 0; j < 4; j++) {
        float4 o;
        o.x = acc[j][0]; o.y = acc[j][1]; o.z = acc[j][2]; o.w = acc[j][3];
        *(float4*)&y[(size_t)(row0 + ty * 4 + j) * DIM + tx * 4] = o;
    }
}

// ---------------------------------------------------------------------------
// Kernel 2: zero the output (harness poisons it with 0xAA).
// ---------------------------------------------------------------------------
__global__ void __launch_bounds__(256) zero_out_kernel(float4* __restrict__ out, int n4)
{
    int i = blockIdx.x * blockDim.x + threadIdx.x;
    const float4 z = {0.f, 0.f, 0.f, 0.f};
    if (i < n4) out[i] = z;
}

// ---------------------------------------------------------------------------
// Kernel 3: out[row] += val * y[col]   (warp per edge, float4 per lane,
// native float4 atomicAdd -> RED.ADD.F32X4, no return). Grid-stride over
// edges so the grid stays modest.
// ---------------------------------------------------------------------------
__global__ void __launch_bounds__(256) scatter_kernel(
    const int*   __restrict__ erow,
    const int*   __restrict__ ecol,
    const float* __restrict__ eval,
    const float* __restrict__ y,
    float*       __restrict__ out)
{
    const int lane        = threadIdx.x & 31;
    const int warps_total = (gridDim.x * blockDim.x) >> 5;
    int e = (blockIdx.x * blockDim.x + threadIdx.x) >> 5;

    for (; e < E_EDGES; e += warps_total) {
        const int   r = __ldg(&erow[e]);   // uniform across warp
        const int   c = __ldg(&ecol[e]);
        const float v = __ldg(&eval[e]);

        const float4 g = *(const float4*)(y + (size_t)c * DIM + lane * 4);
        float4 a;
        a.x = g.x * v; a.y = g.y * v; a.z = g.z * v; a.w = g.w * v;

        atomicAdd((float4*)(out + (size_t)r * DIM + lane * 4), a);
    }
}

// ---------------------------------------------------------------------------
// Launcher. Inputs (metadata order): x, edge_row, edge_col, edge_vals, W.
// ---------------------------------------------------------------------------
extern "C" void kernel_launch(void* const* d_in, const int* in_sizes, int n_in,
                              void* d_out, int out_size)
{
    const float* x    = (const float*)d_in[0];
    const int*   erow = (const int*)  d_in[1];
    const int*   ecol = (const int*)  d_in[2];
    const float* eval = (const float*)d_in[3];
    const float* W    = (const float*)d_in[4];
    float*       out  = (float*)d_out;

    float* y = nullptr;
    cudaGetSymbolAddress((void**)&y, g_y);

    // GEMM: y = x @ W^T
    const int smem_bytes = (128 * WT_STRIDE + RB * DIM) * (int)sizeof(float);
    cudaFuncSetAttribute(gemm_xwt_kernel,
                         cudaFuncAttributeMaxDynamicSharedMemorySize, smem_bytes);
    gemm_xwt_kernel<<<N_NODES / RB, 256, smem_bytes>>>(x, W, y);

    // Zero output.
    const int n4 = N_NODES * DIM / 4;
    zero_out_kernel<<<(n4 + 255) / 256, 256>>>((float4*)out, n4);

    // Scatter-accumulate: out[row] += val * y[col]
    scatter_kernel<<<2048, 256>>>(erow, ecol, eval, y, out);
}